// round 5
// baseline (speedup 1.0000x reference)
#include <cuda_runtime.h>
#include <cstdint>
#include <math.h>

#define BB 4
#define SS 4096
#define DD 256
#define HH 400
#define BSROWS (BB*SS)

// ---- scratch ----
__device__ float g_Q[BSROWS*DD];
__device__ float g_K[BSROWS*DD];
__device__ float g_V[BSROWS*DD];
__device__ float g_T[BSROWS*DD];
__device__ float g_X[BSROWS*DD];
__device__ float g_Y[BSROWS*DD];
__device__ float g_H[BSROWS*HH];

// ============================================================
// helpers
// ============================================================
__device__ __forceinline__ float tf32r(float x) {
    float r; asm("cvt.rna.tf32.f32 %0, %1;" : "=f"(r) : "f"(x)); return r;
}
__device__ __forceinline__ void mma8(float c[4], const uint32_t a[4], const uint32_t b[2]) {
    asm volatile(
        "mma.sync.aligned.m16n8k8.row.col.f32.tf32.tf32.f32 "
        "{%0,%1,%2,%3}, {%4,%5,%6,%7}, {%8,%9}, {%0,%1,%2,%3};"
        : "+f"(c[0]), "+f"(c[1]), "+f"(c[2]), "+f"(c[3])
        : "r"(a[0]), "r"(a[1]), "r"(a[2]), "r"(a[3]), "r"(b[0]), "r"(b[1]));
}
__device__ __forceinline__ uint32_t f2u(float x) { return __float_as_uint(x); }

// ============================================================
// Flash attention, tf32 HMMA, scalar-LDS fragment gather.
// CTA: 32 queries, 256 threads (8 warps = 2 row-groups x 4 col-quarters).
// K/V chunks of 32 keys. SMEM 105.3KB -> 2 CTAs/SM.
// ============================================================
#define FBQ 32
#define FBK 32
#define QSTR 260
#define KSTR 260
#define VSTR 264
#define SSTR 36
// f32 offsets in dynamic smem
#define OQ  0
#define OK  8320                  // 32*260
#define OV  16640                 // + 32*260
#define OS  25088                 // + 32*264
#define OM  26240                 // + 32*36
#define OL  26272
#define OA  26304
#define FL_FLOATS 26336           // *4 = 105344 bytes

__global__ void __launch_bounds__(256, 2)
flash_mma(const float* __restrict__ Qg, const float* __restrict__ Kg,
          const float* __restrict__ Vg, float* __restrict__ Og, int causal) {
    extern __shared__ float fs[];
    int tid = threadIdx.x;
    int wid = tid >> 5, lane = tid & 31;
    int rg = wid >> 2;        // row-group: rows 16*rg .. +15
    int h  = wid & 3;         // quarter: score cols 8h / O cols 64h
    int lrow = lane >> 2;
    int lcol = lane & 3;
    int b = blockIdx.y, q0 = blockIdx.x * FBQ;

    // ---- stage Q (prescaled by 1/sqrt(4096)=1/64, rna-tf32) ----
    {
        const float4* Qr = (const float4*)(Qg + ((size_t)b * SS + q0) * DD);
        #pragma unroll
        for (int p = 0; p < 8; p++) {
            int idx = tid + p * 256;
            int r = idx >> 6, c4 = idx & 63;
            float4 v = Qr[r * 64 + c4];
            v.x = tf32r(v.x * 0.015625f); v.y = tf32r(v.y * 0.015625f);
            v.z = tf32r(v.z * 0.015625f); v.w = tf32r(v.w * 0.015625f);
            *(float4*)&fs[OQ + r * QSTR + c4 * 4] = v;
        }
    }
    if (tid < FBQ) { fs[OM + tid] = -INFINITY; fs[OL + tid] = 0.0f; }

    float ofrag[8][4];
    #pragma unroll
    for (int nb = 0; nb < 8; nb++)
        #pragma unroll
        for (int j = 0; j < 4; j++) ofrag[nb][j] = 0.0f;

    int nc = causal ? (blockIdx.x + 1) : (SS / FBK);

    for (int c = 0; c < nc; c++) {
        int k0 = c * FBK;
        bool maskc = causal && (k0 == q0);

        // ---- stage K and V (row-major, rna-tf32) ----
        {
            const float4* Kr = (const float4*)(Kg + ((size_t)b * SS + k0) * DD);
            const float4* Vr = (const float4*)(Vg + ((size_t)b * SS + k0) * DD);
            #pragma unroll
            for (int p = 0; p < 8; p++) {
                int idx = tid + p * 256;
                int r = idx >> 6, c4 = idx & 63;
                float4 v = Kr[r * 64 + c4];
                v.x = tf32r(v.x); v.y = tf32r(v.y); v.z = tf32r(v.z); v.w = tf32r(v.w);
                *(float4*)&fs[OK + r * KSTR + c4 * 4] = v;
                float4 w = Vr[r * 64 + c4];
                w.x = tf32r(w.x); w.y = tf32r(w.y); w.z = tf32r(w.z); w.w = tf32r(w.w);
                *(float4*)&fs[OV + r * VSTR + c4 * 4] = w;
            }
        }
        __syncthreads();   // (A)

        // ---- scores: warp (rg,h): S[16rg..+15][8h..+7] ----
        {
            float sfr[4] = {0.f, 0.f, 0.f, 0.f};
            #pragma unroll
            for (int kb = 0; kb < 32; kb++) {
                int kk = kb * 8 + lcol;
                uint32_t a[4];
                a[0] = f2u(fs[OQ + (16 * rg + lrow) * QSTR + kk]);
                a[1] = f2u(fs[OQ + (16 * rg + lrow + 8) * QSTR + kk]);
                a[2] = f2u(fs[OQ + (16 * rg + lrow) * QSTR + kk + 4]);
                a[3] = f2u(fs[OQ + (16 * rg + lrow + 8) * QSTR + kk + 4]);
                uint32_t b2[2];
                b2[0] = f2u(fs[OK + (8 * h + lrow) * KSTR + kk]);
                b2[1] = f2u(fs[OK + (8 * h + lrow) * KSTR + kk + 4]);
                mma8(sfr, a, b2);
            }
            int grow0 = q0 + 16 * rg + lrow;
            int cb0 = 8 * h + 2 * lcol;
            float2 v0 = make_float2(sfr[0], sfr[1]);
            float2 v1 = make_float2(sfr[2], sfr[3]);
            if (maskc) {
                int g = k0 + cb0;
                if (g > grow0)         v0.x = -1e30f;
                if (g + 1 > grow0)     v0.y = -1e30f;
                if (g > grow0 + 8)     v1.x = -1e30f;
                if (g + 1 > grow0 + 8) v1.y = -1e30f;
            }
            *(float2*)&fs[OS + (16 * rg + lrow) * SSTR + cb0] = v0;
            *(float2*)&fs[OS + (16 * rg + lrow + 8) * SSTR + cb0] = v1;
        }
        __syncthreads();   // (B)

        // ---- online softmax: 8 threads per row, 4 cols each ----
        {
            int row = tid >> 3, seg = tid & 7;
            float4 x = *(float4*)&fs[OS + row * SSTR + seg * 4];
            float mx = fmaxf(fmaxf(x.x, x.y), fmaxf(x.z, x.w));
            mx = fmaxf(mx, __shfl_xor_sync(0xffffffff, mx, 1));
            mx = fmaxf(mx, __shfl_xor_sync(0xffffffff, mx, 2));
            mx = fmaxf(mx, __shfl_xor_sync(0xffffffff, mx, 4));
            float mold = fs[OM + row];
            float mnew = fmaxf(mold, mx);
            float alpha = __expf(mold - mnew);
            x.x = __expf(x.x - mnew); x.y = __expf(x.y - mnew);
            x.z = __expf(x.z - mnew); x.w = __expf(x.w - mnew);
            float sum = x.x + x.y + x.z + x.w;
            x.x = tf32r(x.x); x.y = tf32r(x.y); x.z = tf32r(x.z); x.w = tf32r(x.w);
            *(float4*)&fs[OS + row * SSTR + seg * 4] = x;
            sum += __shfl_xor_sync(0xffffffff, sum, 1);
            sum += __shfl_xor_sync(0xffffffff, sum, 2);
            sum += __shfl_xor_sync(0xffffffff, sum, 4);
            if (seg == 0) {
                fs[OL + row] = fs[OL + row] * alpha + sum;
                fs[OM + row] = mnew;
                fs[OA + row] = alpha;
            }
        }
        __syncthreads();   // (C)

        // ---- PV: warp (rg,h): O[16rg..+15][64h..+63] += P * V ----
        {
            float al0 = fs[OA + 16 * rg + lrow];
            float al8 = fs[OA + 16 * rg + lrow + 8];
            #pragma unroll
            for (int nb = 0; nb < 8; nb++) {
                ofrag[nb][0] *= al0; ofrag[nb][1] *= al0;
                ofrag[nb][2] *= al8; ofrag[nb][3] *= al8;
            }
            #pragma unroll
            for (int kb = 0; kb < 4; kb++) {
                int kk = kb * 8 + lcol;
                uint32_t a[4];
                a[0] = f2u(fs[OS + (16 * rg + lrow) * SSTR + kk]);
                a[1] = f2u(fs[OS + (16 * rg + lrow + 8) * SSTR + kk]);
                a[2] = f2u(fs[OS + (16 * rg + lrow) * SSTR + kk + 4]);
                a[3] = f2u(fs[OS + (16 * rg + lrow + 8) * SSTR + kk + 4]);
                #pragma unroll
                for (int nb = 0; nb < 8; nb++) {
                    int ncol = 64 * h + nb * 8 + lrow;
                    uint32_t b2[2];
                    b2[0] = f2u(fs[OV + kk * VSTR + ncol]);
                    b2[1] = f2u(fs[OV + (kk + 4) * VSTR + ncol]);
                    mma8(ofrag[nb], a, b2);
                }
            }
        }
        __syncthreads();   // (D)
    }

    // ---- epilogue ----
    {
        int row = 16 * rg + lrow;
        float inv0 = 1.0f / fs[OL + row];
        float inv8 = 1.0f / fs[OL + row + 8];
        float* Or0 = Og + ((size_t)b * SS + q0 + row) * DD;
        float* Or8 = Or0 + 8 * DD;
        #pragma unroll
        for (int nb = 0; nb < 8; nb++) {
            int col = 64 * h + nb * 8 + 2 * lcol;
            *(float2*)&Or0[col] = make_float2(ofrag[nb][0] * inv0, ofrag[nb][1] * inv0);
            *(float2*)&Or8[col] = make_float2(ofrag[nb][2] * inv8, ofrag[nb][3] * inv8);
        }
    }
}

// ============================================================
// tf32 HMMA GEMM, double-buffered: C[M,N]=A[M,K]*W[K,N] (+bias,+leaky)
// BM=64, BN=64, BK=16, 256 threads (8 warps = 4m x 2n).
// M%64==0, K%16==0 required; N guarded.
// ============================================================
#define ASTR 20
#define WSTR 72

template<int BIAS, int LEAKY>
__global__ void __launch_bounds__(256)
gemm_tc(const float* __restrict__ A, const float* __restrict__ W,
        const float* __restrict__ bias, float* __restrict__ C,
        int M, int N, int K) {
    __shared__ float As[2][64 * ASTR];
    __shared__ float Ws[2][16 * WSTR];
    int tid = threadIdx.x;
    int wid = tid >> 5, lane = tid & 31;
    int wm = wid & 3, wn = wid >> 2;
    int lrow = lane >> 2, lcol = lane & 3;
    int rb = blockIdx.y * 64, cb = blockIdx.x * 64;

    int arow = tid >> 2, akq = (tid & 3) * 4;
    int wkk = tid >> 4, wn4 = tid & 15;
    int wcol = cb + wn4 * 4;

    float cfr[4][4];
    #pragma unroll
    for (int nb = 0; nb < 4; nb++)
        #pragma unroll
        for (int j = 0; j < 4; j++) cfr[nb][j] = 0.0f;

    // ---- prologue: load+store k0=0 ----
    {
        float4 va = *(const float4*)&A[(size_t)(rb + arow) * K + akq];
        va.x = tf32r(va.x); va.y = tf32r(va.y); va.z = tf32r(va.z); va.w = tf32r(va.w);
        *(float4*)&As[0][arow * ASTR + akq] = va;
        float4 vw;
        if (wcol + 3 < N) {
            vw = *(const float4*)&W[(size_t)wkk * N + wcol];
        } else {
            vw.x = (wcol + 0 < N) ? W[(size_t)wkk * N + wcol + 0] : 0.0f;
            vw.y = (wcol + 1 < N) ? W[(size_t)wkk * N + wcol + 1] : 0.0f;
            vw.z = (wcol + 2 < N) ? W[(size_t)wkk * N + wcol + 2] : 0.0f;
            vw.w = (wcol + 3 < N) ? W[(size_t)wkk * N + wcol + 3] : 0.0f;
        }
        vw.x = tf32r(vw.x); vw.y = tf32r(vw.y); vw.z = tf32r(vw.z); vw.w = tf32r(vw.w);
        *(float4*)&Ws[0][wkk * WSTR + wn4 * 4] = vw;
    }
    __syncthreads();

    int buf = 0;
    for (int k0 = 0; k0 < K; k0 += 16) {
        bool more = (k0 + 16) < K;
        float4 na, nw;
        if (more) {
            na = *(const float4*)&A[(size_t)(rb + arow) * K + k0 + 16 + akq];
            if (wcol + 3 < N) {
                nw = *(const float4*)&W[(size_t)(k0 + 16 + wkk) * N + wcol];
            } else {
                nw.x = (wcol + 0 < N) ? W[(size_t)(k0 + 16 + wkk) * N + wcol + 0] : 0.0f;
                nw.y = (wcol + 1 < N) ? W[(size_t)(k0 + 16 + wkk) * N + wcol + 1] : 0.0f;
                nw.z = (wcol + 2 < N) ? W[(size_t)(k0 + 16 + wkk) * N + wcol + 2] : 0.0f;
                nw.w = (wcol + 3 < N) ? W[(size_t)(k0 + 16 + wkk) * N + wcol + 3] : 0.0f;
            }
        }
        // ---- compute on current buffer ----
        #pragma unroll
        for (int kb = 0; kb < 2; kb++) {
            int kk = kb * 8 + lcol;
            uint32_t a[4];
            a[0] = f2u(As[buf][(16 * wm + lrow) * ASTR + kk]);
            a[1] = f2u(As[buf][(16 * wm + lrow + 8) * ASTR + kk]);
            a[2] = f2u(As[buf][(16 * wm + lrow) * ASTR + kk + 4]);
            a[3] = f2u(As[buf][(16 * wm + lrow + 8) * ASTR + kk + 4]);
            #pragma unroll
            for (int nb = 0; nb < 4; nb++) {
                int ncol = 32 * wn + nb * 8 + lrow;
                uint32_t b2[2];
                b2[0] = f2u(Ws[buf][kk * WSTR + ncol]);
                b2[1] = f2u(Ws[buf][(kk + 4) * WSTR + ncol]);
                mma8(cfr[nb], a, b2);
            }
        }
        if (more) {
            na.x = tf32r(na.x); na.y = tf32r(na.y); na.z = tf32r(na.z); na.w = tf32r(na.w);
            *(float4*)&As[buf ^ 1][arow * ASTR + akq] = na;
            nw.x = tf32r(nw.x); nw.y = tf32r(nw.y); nw.z = tf32r(nw.z); nw.w = tf32r(nw.w);
            *(float4*)&Ws[buf ^ 1][wkk * WSTR + wn4 * 4] = nw;
        }
        __syncthreads();
        buf ^= 1;
    }

    // ---- epilogue ----
    int r0 = rb + 16 * wm + lrow;
    #pragma unroll
    for (int nb = 0; nb < 4; nb++) {
        int col = cb + 32 * wn + nb * 8 + 2 * lcol;
        if (col < N) {
            float v00 = cfr[nb][0], v01 = cfr[nb][1];
            float v10 = cfr[nb][2], v11 = cfr[nb][3];
            if (BIAS) {
                float b0 = bias[col], b1 = bias[col + 1];
                v00 += b0; v01 += b1; v10 += b0; v11 += b1;
            }
            if (LEAKY) {
                v00 = (v00 > 0.0f) ? v00 : 0.2f * v00;
                v01 = (v01 > 0.0f) ? v01 : 0.2f * v01;
                v10 = (v10 > 0.0f) ? v10 : 0.2f * v10;
                v11 = (v11 > 0.0f) ? v11 : 0.2f * v11;
            }
            *(float2*)&C[(size_t)r0 * N + col] = make_float2(v00, v01);
            *(float2*)&C[(size_t)(r0 + 8) * N + col] = make_float2(v10, v11);
        }
    }
}

// ============================================================
// out = LayerNorm(a + b), eps = 1e-3.  One warp per row (8 rows/block).
// ============================================================
__global__ void __launch_bounds__(256)
add_ln_kernel(const float* __restrict__ a, const float* __restrict__ bvec,
              const float* __restrict__ gamma, const float* __restrict__ beta,
              float* __restrict__ out) {
    int wid = threadIdx.x >> 5, lane = threadIdx.x & 31;
    int row = blockIdx.x * 8 + wid;
    const float4* ar = (const float4*)(a + (size_t)row * DD);
    const float4* br = (const float4*)(bvec + (size_t)row * DD);
    float4 v0 = ar[lane];        float4 w0 = br[lane];
    float4 v1 = ar[lane + 32];   float4 w1 = br[lane + 32];
    v0.x += w0.x; v0.y += w0.y; v0.z += w0.z; v0.w += w0.w;
    v1.x += w1.x; v1.y += w1.y; v1.z += w1.z; v1.w += w1.w;

    float sum = v0.x + v0.y + v0.z + v0.w + v1.x + v1.y + v1.z + v1.w;
    #pragma unroll
    for (int off = 16; off > 0; off >>= 1) sum += __shfl_xor_sync(0xffffffff, sum, off);
    float mu = sum * (1.0f / DD);

    float sq = (v0.x - mu) * (v0.x - mu) + (v0.y - mu) * (v0.y - mu)
             + (v0.z - mu) * (v0.z - mu) + (v0.w - mu) * (v0.w - mu)
             + (v1.x - mu) * (v1.x - mu) + (v1.y - mu) * (v1.y - mu)
             + (v1.z - mu) * (v1.z - mu) + (v1.w - mu) * (v1.w - mu);
    #pragma unroll
    for (int off = 16; off > 0; off >>= 1) sq += __shfl_xor_sync(0xffffffff, sq, off);
    float rs = rsqrtf(sq * (1.0f / DD) + 1e-3f);

    const float4* g4 = (const float4*)gamma;
    const float4* b4 = (const float4*)beta;
    float4 g0 = g4[lane], g1 = g4[lane + 32];
    float4 e0 = b4[lane], e1 = b4[lane + 32];
    float4 o0, o1;
    o0.x = (v0.x - mu) * rs * g0.x + e0.x;
    o0.y = (v0.y - mu) * rs * g0.y + e0.y;
    o0.z = (v0.z - mu) * rs * g0.z + e0.z;
    o0.w = (v0.w - mu) * rs * g0.w + e0.w;
    o1.x = (v1.x - mu) * rs * g1.x + e1.x;
    o1.y = (v1.y - mu) * rs * g1.y + e1.y;
    o1.z = (v1.z - mu) * rs * g1.z + e1.z;
    o1.w = (v1.w - mu) * rs * g1.w + e1.w;
    float4* orow = (float4*)(out + (size_t)row * DD);
    orow[lane] = o0;
    orow[lane + 32] = o1;
}

// ============================================================
extern "C" void kernel_launch(void* const* d_in, const int* in_sizes, int n_in,
                              void* d_out, int out_size) {
    const float* inputs = (const float*)d_in[0];
    const float* ctx    = (const float*)d_in[1];
    const float* sa_Wk  = (const float*)d_in[2];
    const float* sa_Wv  = (const float*)d_in[3];
    const float* sa_Wq  = (const float*)d_in[4];
    const float* ca_Wk  = (const float*)d_in[5];
    const float* ca_Wv  = (const float*)d_in[6];
    const float* ca_Wq  = (const float*)d_in[7];
    const float* W1     = (const float*)d_in[8];
    const float* b1     = (const float*)d_in[9];
    const float* W2     = (const float*)d_in[10];
    const float* b2     = (const float*)d_in[11];
    const float* gamma  = (const float*)d_in[12];
    const float* beta   = (const float*)d_in[13];
    float* out = (float*)d_out;

    float *Qp, *Kp, *Vp, *Tp, *Xp, *Yp, *Hp;
    cudaGetSymbolAddress((void**)&Qp, g_Q);
    cudaGetSymbolAddress((void**)&Kp, g_K);
    cudaGetSymbolAddress((void**)&Vp, g_V);
    cudaGetSymbolAddress((void**)&Tp, g_T);
    cudaGetSymbolAddress((void**)&Xp, g_X);
    cudaGetSymbolAddress((void**)&Yp, g_Y);
    cudaGetSymbolAddress((void**)&Hp, g_H);

    const int flash_smem = FL_FLOATS * 4;
    cudaFuncSetAttribute(flash_mma, cudaFuncAttributeMaxDynamicSharedMemorySize, flash_smem);

    dim3 gD(DD / 64, BSROWS / 64);
    dim3 gH((HH + 63) / 64, BSROWS / 64);
    dim3 fg(SS / FBQ, BB);
    int lnB = BSROWS / 8;

    // 1) self-attention (causal)
    gemm_tc<0, 0><<<gD, 256>>>(inputs, sa_Wk, nullptr, Kp, BSROWS, DD, DD);
    gemm_tc<0, 0><<<gD, 256>>>(inputs, sa_Wv, nullptr, Vp, BSROWS, DD, DD);
    gemm_tc<0, 0><<<gD, 256>>>(inputs, sa_Wq, nullptr, Qp, BSROWS, DD, DD);
    flash_mma<<<fg, 256, flash_smem>>>(Qp, Kp, Vp, Tp, 1);
    add_ln_kernel<<<lnB, 256>>>(Tp, inputs, gamma, beta, Xp);

    // 2) cross-attention
    gemm_tc<0, 0><<<gD, 256>>>(ctx, ca_Wk, nullptr, Kp, BSROWS, DD, DD);
    gemm_tc<0, 0><<<gD, 256>>>(ctx, ca_Wv, nullptr, Vp, BSROWS, DD, DD);
    gemm_tc<0, 0><<<gD, 256>>>(Xp, ca_Wq, nullptr, Qp, BSROWS, DD, DD);
    flash_mma<<<fg, 256, flash_smem>>>(Qp, Kp, Vp, Tp, 0);
    add_ln_kernel<<<lnB, 256>>>(Tp, Xp, gamma, beta, Yp);

    // 3) FFN
    gemm_tc<1, 1><<<gH, 256>>>(Yp, W1, b1, Hp, BSROWS, HH, DD);
    gemm_tc<1, 0><<<gD, 256>>>(Hp, W2, b2, Tp, BSROWS, DD, HH);
    add_ln_kernel<<<lnB, 256>>>(Tp, Yp, gamma, beta, out);
}

// round 6
// speedup vs baseline: 1.2062x; 1.2062x over previous
#include <cuda_runtime.h>
#include <cstdint>
#include <math.h>

#define BB 4
#define SS 4096
#define DD 256
#define HH 400
#define BSROWS (BB*SS)

// ---- scratch ----
__device__ float g_Q[BSROWS*DD];
__device__ float g_K[BSROWS*DD];
__device__ float g_V[BSROWS*DD];
__device__ float g_T[BSROWS*DD];
__device__ float g_X[BSROWS*DD];
__device__ float g_Y[BSROWS*DD];
__device__ float g_H[BSROWS*HH];

// ============================================================
// helpers
// ============================================================
__device__ __forceinline__ float tf32r(float x) {
    float r; asm("cvt.rna.tf32.f32 %0, %1;" : "=f"(r) : "f"(x)); return r;
}
__device__ __forceinline__ void mma8(float c[4], const uint32_t a[4], const uint32_t b[2]) {
    asm volatile(
        "mma.sync.aligned.m16n8k8.row.col.f32.tf32.tf32.f32 "
        "{%0,%1,%2,%3}, {%4,%5,%6,%7}, {%8,%9}, {%0,%1,%2,%3};"
        : "+f"(c[0]), "+f"(c[1]), "+f"(c[2]), "+f"(c[3])
        : "r"(a[0]), "r"(a[1]), "r"(a[2]), "r"(a[3]), "r"(b[0]), "r"(b[1]));
}
__device__ __forceinline__ uint32_t f2u(float x) { return __float_as_uint(x); }

// ============================================================
// Flash attention, tf32 HMMA, scalar-LDS fragment gather.
// CTA: 64 queries, 512 threads (16 warps = 4 row-groups x 4 col-quarters).
// K/V chunks of 64 keys. Same SMEM as round-3 (218.9 KB), 2x warps.
// ============================================================
#define FBQ 64
#define FBK 64
#define QSTR 260
#define KSTR 260
#define VSTR 264
#define SSTR 68
// f32 offsets in dynamic smem
#define OQ  0
#define OK  16640                 // 64*260
#define OV  33280                 // + 64*260
#define OS  50176                 // + 64*264
#define OM  54528                 // + 64*68
#define OL  54592
#define OA  54656
#define FL_FLOATS 54720           // *4 = 218880 bytes

__global__ void __launch_bounds__(512, 1)
flash_mma(const float* __restrict__ Qg, const float* __restrict__ Kg,
          const float* __restrict__ Vg, float* __restrict__ Og, int causal) {
    extern __shared__ float fs[];
    int tid = threadIdx.x;
    int wid = tid >> 5, lane = tid & 31;
    int rg = wid >> 2;        // row-group: rows 16*rg .. +15
    int h  = wid & 3;         // quarter: score cols 16h..+15 / O cols 64h..+63
    int lrow = lane >> 2;
    int lcol = lane & 3;
    int b = blockIdx.y, q0 = blockIdx.x * FBQ;

    // ---- stage Q (prescaled by 1/sqrt(4096)=1/64, rna-tf32) ----
    {
        const float4* Qr = (const float4*)(Qg + ((size_t)b * SS + q0) * DD);
        #pragma unroll
        for (int p = 0; p < 8; p++) {
            int idx = tid + p * 512;
            int r = idx >> 6, c4 = idx & 63;
            float4 v = Qr[r * 64 + c4];
            v.x = tf32r(v.x * 0.015625f); v.y = tf32r(v.y * 0.015625f);
            v.z = tf32r(v.z * 0.015625f); v.w = tf32r(v.w * 0.015625f);
            *(float4*)&fs[OQ + r * QSTR + c4 * 4] = v;
        }
    }
    if (tid < FBQ) { fs[OM + tid] = -INFINITY; fs[OL + tid] = 0.0f; }

    float ofrag[8][4];
    #pragma unroll
    for (int nb = 0; nb < 8; nb++)
        #pragma unroll
        for (int j = 0; j < 4; j++) ofrag[nb][j] = 0.0f;

    int nc = causal ? (blockIdx.x + 1) : (SS / FBK);

    for (int c = 0; c < nc; c++) {
        int k0 = c * FBK;
        bool maskc = causal && (k0 == q0);

        // ---- stage K and V (row-major, rna-tf32) ----
        {
            const float4* Kr = (const float4*)(Kg + ((size_t)b * SS + k0) * DD);
            const float4* Vr = (const float4*)(Vg + ((size_t)b * SS + k0) * DD);
            #pragma unroll
            for (int p = 0; p < 8; p++) {
                int idx = tid + p * 512;
                int r = idx >> 6, c4 = idx & 63;
                float4 v = Kr[r * 64 + c4];
                v.x = tf32r(v.x); v.y = tf32r(v.y); v.z = tf32r(v.z); v.w = tf32r(v.w);
                *(float4*)&fs[OK + r * KSTR + c4 * 4] = v;
                float4 w = Vr[r * 64 + c4];
                w.x = tf32r(w.x); w.y = tf32r(w.y); w.z = tf32r(w.z); w.w = tf32r(w.w);
                *(float4*)&fs[OV + r * VSTR + c4 * 4] = w;
            }
        }
        __syncthreads();   // (A)

        // ---- scores: warp (rg,h): S[16rg..+15][16h..+15] ----
        {
            float sfr[2][4];
            #pragma unroll
            for (int nb = 0; nb < 2; nb++)
                #pragma unroll
                for (int j = 0; j < 4; j++) sfr[nb][j] = 0.0f;

            #pragma unroll 8
            for (int kb = 0; kb < 32; kb++) {
                int kk = kb * 8 + lcol;
                uint32_t a[4];
                a[0] = f2u(fs[OQ + (16 * rg + lrow) * QSTR + kk]);
                a[1] = f2u(fs[OQ + (16 * rg + lrow + 8) * QSTR + kk]);
                a[2] = f2u(fs[OQ + (16 * rg + lrow) * QSTR + kk + 4]);
                a[3] = f2u(fs[OQ + (16 * rg + lrow + 8) * QSTR + kk + 4]);
                #pragma unroll
                for (int nb = 0; nb < 2; nb++) {
                    int nrow = 16 * h + nb * 8 + lrow;
                    uint32_t b2[2];
                    b2[0] = f2u(fs[OK + nrow * KSTR + kk]);
                    b2[1] = f2u(fs[OK + nrow * KSTR + kk + 4]);
                    mma8(sfr[nb], a, b2);
                }
            }
            int grow0 = q0 + 16 * rg + lrow;
            #pragma unroll
            for (int nb = 0; nb < 2; nb++) {
                int cb0 = 16 * h + nb * 8 + 2 * lcol;
                float2 v0 = make_float2(sfr[nb][0], sfr[nb][1]);
                float2 v1 = make_float2(sfr[nb][2], sfr[nb][3]);
                if (maskc) {
                    int g = k0 + cb0;
                    if (g > grow0)         v0.x = -1e30f;
                    if (g + 1 > grow0)     v0.y = -1e30f;
                    if (g > grow0 + 8)     v1.x = -1e30f;
                    if (g + 1 > grow0 + 8) v1.y = -1e30f;
                }
                *(float2*)&fs[OS + (16 * rg + lrow) * SSTR + cb0] = v0;
                *(float2*)&fs[OS + (16 * rg + lrow + 8) * SSTR + cb0] = v1;
            }
        }
        __syncthreads();   // (B)

        // ---- online softmax: 8 threads per row, 8 cols each ----
        {
            int row = tid >> 3, seg = tid & 7;
            float* Sr = &fs[OS + row * SSTR + seg * 8];
            float4 x0 = ((float4*)Sr)[0];
            float4 x1 = ((float4*)Sr)[1];
            float mx = fmaxf(fmaxf(fmaxf(x0.x, x0.y), fmaxf(x0.z, x0.w)),
                             fmaxf(fmaxf(x1.x, x1.y), fmaxf(x1.z, x1.w)));
            mx = fmaxf(mx, __shfl_xor_sync(0xffffffff, mx, 1));
            mx = fmaxf(mx, __shfl_xor_sync(0xffffffff, mx, 2));
            mx = fmaxf(mx, __shfl_xor_sync(0xffffffff, mx, 4));
            float mold = fs[OM + row];
            float mnew = fmaxf(mold, mx);
            float alpha = __expf(mold - mnew);
            x0.x = __expf(x0.x - mnew); x0.y = __expf(x0.y - mnew);
            x0.z = __expf(x0.z - mnew); x0.w = __expf(x0.w - mnew);
            x1.x = __expf(x1.x - mnew); x1.y = __expf(x1.y - mnew);
            x1.z = __expf(x1.z - mnew); x1.w = __expf(x1.w - mnew);
            float sum = x0.x + x0.y + x0.z + x0.w + x1.x + x1.y + x1.z + x1.w;
            x0.x = tf32r(x0.x); x0.y = tf32r(x0.y); x0.z = tf32r(x0.z); x0.w = tf32r(x0.w);
            x1.x = tf32r(x1.x); x1.y = tf32r(x1.y); x1.z = tf32r(x1.z); x1.w = tf32r(x1.w);
            ((float4*)Sr)[0] = x0;
            ((float4*)Sr)[1] = x1;
            sum += __shfl_xor_sync(0xffffffff, sum, 1);
            sum += __shfl_xor_sync(0xffffffff, sum, 2);
            sum += __shfl_xor_sync(0xffffffff, sum, 4);
            if (seg == 0) {
                fs[OL + row] = fs[OL + row] * alpha + sum;
                fs[OM + row] = mnew;
                fs[OA + row] = alpha;
            }
        }
        __syncthreads();   // (C)

        // ---- PV: warp (rg,h): O[16rg..+15][64h..+63] += P * V ----
        {
            float al0 = fs[OA + 16 * rg + lrow];
            float al8 = fs[OA + 16 * rg + lrow + 8];
            #pragma unroll
            for (int nb = 0; nb < 8; nb++) {
                ofrag[nb][0] *= al0; ofrag[nb][1] *= al0;
                ofrag[nb][2] *= al8; ofrag[nb][3] *= al8;
            }
            #pragma unroll
            for (int kb = 0; kb < 8; kb++) {
                int kk = kb * 8 + lcol;
                uint32_t a[4];
                a[0] = f2u(fs[OS + (16 * rg + lrow) * SSTR + kk]);
                a[1] = f2u(fs[OS + (16 * rg + lrow + 8) * SSTR + kk]);
                a[2] = f2u(fs[OS + (16 * rg + lrow) * SSTR + kk + 4]);
                a[3] = f2u(fs[OS + (16 * rg + lrow + 8) * SSTR + kk + 4]);
                #pragma unroll
                for (int nb = 0; nb < 8; nb++) {
                    int ncol = 64 * h + nb * 8 + lrow;
                    uint32_t b2[2];
                    b2[0] = f2u(fs[OV + kk * VSTR + ncol]);
                    b2[1] = f2u(fs[OV + (kk + 4) * VSTR + ncol]);
                    mma8(ofrag[nb], a, b2);
                }
            }
        }
        __syncthreads();   // (D)
    }

    // ---- epilogue ----
    {
        int row = 16 * rg + lrow;
        float inv0 = 1.0f / fs[OL + row];
        float inv8 = 1.0f / fs[OL + row + 8];
        float* Or0 = Og + ((size_t)b * SS + q0 + row) * DD;
        float* Or8 = Or0 + 8 * DD;
        #pragma unroll
        for (int nb = 0; nb < 8; nb++) {
            int col = 64 * h + nb * 8 + 2 * lcol;
            *(float2*)&Or0[col] = make_float2(ofrag[nb][0] * inv0, ofrag[nb][1] * inv0);
            *(float2*)&Or8[col] = make_float2(ofrag[nb][2] * inv8, ofrag[nb][3] * inv8);
        }
    }
}

// ============================================================
// tf32 HMMA GEMM (round-3 proven): C[M,N]=A[M,K]*W[K,N] (+bias,+leaky)
// BM=64, BN=64, BK=16, 256 threads (8 warps = 4m x 2n).
// ============================================================
#define ASTR 20
#define WSTR 72

template<int BIAS, int LEAKY>
__global__ void __launch_bounds__(256)
gemm_tc(const float* __restrict__ A, const float* __restrict__ W,
        const float* __restrict__ bias, float* __restrict__ C,
        int M, int N, int K) {
    __shared__ float As[64 * ASTR];
    __shared__ float Ws[16 * WSTR];
    int tid = threadIdx.x;
    int wid = tid >> 5, lane = tid & 31;
    int wm = wid & 3, wn = wid >> 2;
    int lrow = lane >> 2, lcol = lane & 3;
    int rb = blockIdx.y * 64, cb = blockIdx.x * 64;

    float cfr[4][4];
    #pragma unroll
    for (int nb = 0; nb < 4; nb++)
        #pragma unroll
        for (int j = 0; j < 4; j++) cfr[nb][j] = 0.0f;

    for (int k0 = 0; k0 < K; k0 += 16) {
        // stage A tile 64x16
        {
            int row = tid >> 2, kq = tid & 3;
            float4 v = *(const float4*)&A[(size_t)(rb + row) * K + k0 + kq * 4];
            v.x = tf32r(v.x); v.y = tf32r(v.y); v.z = tf32r(v.z); v.w = tf32r(v.w);
            *(float4*)&As[row * ASTR + kq * 4] = v;
        }
        // stage W tile 16x64
        {
            int kk = tid >> 4, n4 = tid & 15;
            int col = cb + n4 * 4;
            float4 v;
            if (col + 3 < N) {
                v = *(const float4*)&W[(size_t)(k0 + kk) * N + col];
            } else {
                v.x = (col + 0 < N) ? W[(size_t)(k0 + kk) * N + col + 0] : 0.0f;
                v.y = (col + 1 < N) ? W[(size_t)(k0 + kk) * N + col + 1] : 0.0f;
                v.z = (col + 2 < N) ? W[(size_t)(k0 + kk) * N + col + 2] : 0.0f;
                v.w = (col + 3 < N) ? W[(size_t)(k0 + kk) * N + col + 3] : 0.0f;
            }
            v.x = tf32r(v.x); v.y = tf32r(v.y); v.z = tf32r(v.z); v.w = tf32r(v.w);
            *(float4*)&Ws[kk * WSTR + n4 * 4] = v;
        }
        __syncthreads();
        #pragma unroll
        for (int kb = 0; kb < 2; kb++) {
            int kk = kb * 8 + lcol;
            uint32_t a[4];
            a[0] = f2u(As[(16 * wm + lrow) * ASTR + kk]);
            a[1] = f2u(As[(16 * wm + lrow + 8) * ASTR + kk]);
            a[2] = f2u(As[(16 * wm + lrow) * ASTR + kk + 4]);
            a[3] = f2u(As[(16 * wm + lrow + 8) * ASTR + kk + 4]);
            #pragma unroll
            for (int nb = 0; nb < 4; nb++) {
                int ncol = 32 * wn + nb * 8 + lrow;
                uint32_t b2[2];
                b2[0] = f2u(Ws[kk * WSTR + ncol]);
                b2[1] = f2u(Ws[(kk + 4) * WSTR + ncol]);
                mma8(cfr[nb], a, b2);
            }
        }
        __syncthreads();
    }

    // epilogue
    int r0 = rb + 16 * wm + lrow;
    #pragma unroll
    for (int nb = 0; nb < 4; nb++) {
        int col = cb + 32 * wn + nb * 8 + 2 * lcol;
        if (col < N) {
            float v00 = cfr[nb][0], v01 = cfr[nb][1];
            float v10 = cfr[nb][2], v11 = cfr[nb][3];
            if (BIAS) {
                float b0 = bias[col], b1 = bias[col + 1];
                v00 += b0; v01 += b1; v10 += b0; v11 += b1;
            }
            if (LEAKY) {
                v00 = (v00 > 0.0f) ? v00 : 0.2f * v00;
                v01 = (v01 > 0.0f) ? v01 : 0.2f * v01;
                v10 = (v10 > 0.0f) ? v10 : 0.2f * v10;
                v11 = (v11 > 0.0f) ? v11 : 0.2f * v11;
            }
            *(float2*)&C[(size_t)r0 * N + col] = make_float2(v00, v01);
            *(float2*)&C[(size_t)(r0 + 8) * N + col] = make_float2(v10, v11);
        }
    }
}

// ============================================================
// out = LayerNorm(a + b), eps = 1e-3.  One warp per row (8 rows/block).
// ============================================================
__global__ void __launch_bounds__(256)
add_ln_kernel(const float* __restrict__ a, const float* __restrict__ bvec,
              const float* __restrict__ gamma, const float* __restrict__ beta,
              float* __restrict__ out) {
    int wid = threadIdx.x >> 5, lane = threadIdx.x & 31;
    int row = blockIdx.x * 8 + wid;
    const float4* ar = (const float4*)(a + (size_t)row * DD);
    const float4* br = (const float4*)(bvec + (size_t)row * DD);
    float4 v0 = ar[lane];        float4 w0 = br[lane];
    float4 v1 = ar[lane + 32];   float4 w1 = br[lane + 32];
    v0.x += w0.x; v0.y += w0.y; v0.z += w0.z; v0.w += w0.w;
    v1.x += w1.x; v1.y += w1.y; v1.z += w1.z; v1.w += w1.w;

    float sum = v0.x + v0.y + v0.z + v0.w + v1.x + v1.y + v1.z + v1.w;
    #pragma unroll
    for (int off = 16; off > 0; off >>= 1) sum += __shfl_xor_sync(0xffffffff, sum, off);
    float mu = sum * (1.0f / DD);

    float sq = (v0.x - mu) * (v0.x - mu) + (v0.y - mu) * (v0.y - mu)
             + (v0.z - mu) * (v0.z - mu) + (v0.w - mu) * (v0.w - mu)
             + (v1.x - mu) * (v1.x - mu) + (v1.y - mu) * (v1.y - mu)
             + (v1.z - mu) * (v1.z - mu) + (v1.w - mu) * (v1.w - mu);
    #pragma unroll
    for (int off = 16; off > 0; off >>= 1) sq += __shfl_xor_sync(0xffffffff, sq, off);
    float rs = rsqrtf(sq * (1.0f / DD) + 1e-3f);

    const float4* g4 = (const float4*)gamma;
    const float4* b4 = (const float4*)beta;
    float4 g0 = g4[lane], g1 = g4[lane + 32];
    float4 e0 = b4[lane], e1 = b4[lane + 32];
    float4 o0, o1;
    o0.x = (v0.x - mu) * rs * g0.x + e0.x;
    o0.y = (v0.y - mu) * rs * g0.y + e0.y;
    o0.z = (v0.z - mu) * rs * g0.z + e0.z;
    o0.w = (v0.w - mu) * rs * g0.w + e0.w;
    o1.x = (v1.x - mu) * rs * g1.x + e1.x;
    o1.y = (v1.y - mu) * rs * g1.y + e1.y;
    o1.z = (v1.z - mu) * rs * g1.z + e1.z;
    o1.w = (v1.w - mu) * rs * g1.w + e1.w;
    float4* orow = (float4*)(out + (size_t)row * DD);
    orow[lane] = o0;
    orow[lane + 32] = o1;
}

// ============================================================
extern "C" void kernel_launch(void* const* d_in, const int* in_sizes, int n_in,
                              void* d_out, int out_size) {
    const float* inputs = (const float*)d_in[0];
    const float* ctx    = (const float*)d_in[1];
    const float* sa_Wk  = (const float*)d_in[2];
    const float* sa_Wv  = (const float*)d_in[3];
    const float* sa_Wq  = (const float*)d_in[4];
    const float* ca_Wk  = (const float*)d_in[5];
    const float* ca_Wv  = (const float*)d_in[6];
    const float* ca_Wq  = (const float*)d_in[7];
    const float* W1     = (const float*)d_in[8];
    const float* b1     = (const float*)d_in[9];
    const float* W2     = (const float*)d_in[10];
    const float* b2     = (const float*)d_in[11];
    const float* gamma  = (const float*)d_in[12];
    const float* beta   = (const float*)d_in[13];
    float* out = (float*)d_out;

    float *Qp, *Kp, *Vp, *Tp, *Xp, *Yp, *Hp;
    cudaGetSymbolAddress((void**)&Qp, g_Q);
    cudaGetSymbolAddress((void**)&Kp, g_K);
    cudaGetSymbolAddress((void**)&Vp, g_V);
    cudaGetSymbolAddress((void**)&Tp, g_T);
    cudaGetSymbolAddress((void**)&Xp, g_X);
    cudaGetSymbolAddress((void**)&Yp, g_Y);
    cudaGetSymbolAddress((void**)&Hp, g_H);

    const int flash_smem = FL_FLOATS * 4;
    cudaFuncSetAttribute(flash_mma, cudaFuncAttributeMaxDynamicSharedMemorySize, flash_smem);

    dim3 gD(DD / 64, BSROWS / 64);
    dim3 gH((HH + 63) / 64, BSROWS / 64);
    dim3 fg(SS / FBQ, BB);
    int lnB = BSROWS / 8;

    // 1) self-attention (causal)
    gemm_tc<0, 0><<<gD, 256>>>(inputs, sa_Wk, nullptr, Kp, BSROWS, DD, DD);
    gemm_tc<0, 0><<<gD, 256>>>(inputs, sa_Wv, nullptr, Vp, BSROWS, DD, DD);
    gemm_tc<0, 0><<<gD, 256>>>(inputs, sa_Wq, nullptr, Qp, BSROWS, DD, DD);
    flash_mma<<<fg, 512, flash_smem>>>(Qp, Kp, Vp, Tp, 1);
    add_ln_kernel<<<lnB, 256>>>(Tp, inputs, gamma, beta, Xp);

    // 2) cross-attention
    gemm_tc<0, 0><<<gD, 256>>>(ctx, ca_Wk, nullptr, Kp, BSROWS, DD, DD);
    gemm_tc<0, 0><<<gD, 256>>>(ctx, ca_Wv, nullptr, Vp, BSROWS, DD, DD);
    gemm_tc<0, 0><<<gD, 256>>>(Xp, ca_Wq, nullptr, Qp, BSROWS, DD, DD);
    flash_mma<<<fg, 512, flash_smem>>>(Qp, Kp, Vp, Tp, 0);
    add_ln_kernel<<<lnB, 256>>>(Tp, Xp, gamma, beta, Yp);

    // 3) FFN
    gemm_tc<1, 1><<<gH, 256>>>(Yp, W1, b1, Hp, BSROWS, HH, DD);
    gemm_tc<1, 0><<<gD, 256>>>(Hp, W2, b2, Tp, BSROWS, DD, HH);
    add_ln_kernel<<<lnB, 256>>>(Tp, Yp, gamma, beta, out);
}